// round 16
// baseline (speedup 1.0000x reference)
#include <cuda_runtime.h>
#include <cuda_fp16.h>
#include <cstdint>
#include <math.h>

// Problem constants
#define BB 4
#define NN 2048
#define CC 1024
#define HH 16
#define DD 64
#define MM (BB * NN)          // 8192
#define C3 (3 * CC)           // 3072
#define EPSV 1e-6f

// Scratch (16B-aligned)
__device__ __align__(16) float  g_qkv[(size_t)MM * C3];       // 96 MB
__device__ __align__(16) __half g_xh[(size_t)MM * CC];        // 16 MB
__device__ __align__(16) __half g_oh[(size_t)MM * CC];        // 16 MB
__device__ __align__(16) __half g_wqkvTh[(size_t)C3 * CC];    // 6 MB
__device__ __align__(16) __half g_wprojTh[(size_t)CC * CC];   // 2 MB
__device__ __align__(16) __half g_qh[(size_t)BB * HH * NN * DD]; // 16 MB
__device__ __align__(16) __half g_kh[(size_t)BB * HH * NN * DD]; // 16 MB
__device__ __align__(16) __half g_vh[(size_t)BB * HH * NN * DD]; // 16 MB

__device__ __forceinline__ uint32_t f2h2(float lo, float hi) {
    __half2 h = __float22half2_rn(make_float2(lo, hi));
    return *reinterpret_cast<uint32_t*>(&h);
}
__device__ __forceinline__ uint32_t smem_u32(const void* p) {
    uint32_t a;
    asm("{ .reg .u64 t; cvta.to.shared.u64 t, %1; cvt.u32.u64 %0, t; }" : "=r"(a) : "l"(p));
    return a;
}

#define MMA_F16(c, a0, a1, a2, a3, b0, b1)                                     \
    asm volatile(                                                               \
        "mma.sync.aligned.m16n8k16.row.col.f32.f16.f16.f32 "                    \
        "{%0,%1,%2,%3}, {%4,%5,%6,%7}, {%8,%9}, {%0,%1,%2,%3};"                 \
        : "+f"((c)[0]), "+f"((c)[1]), "+f"((c)[2]), "+f"((c)[3])                \
        : "r"(a0), "r"(a1), "r"(a2), "r"(a3), "r"(b0), "r"(b1))

#define LDM_X4(r0, r1, r2, r3, addr)                                           \
    asm volatile("ldmatrix.sync.aligned.m8n8.x4.shared.b16 {%0,%1,%2,%3}, [%4];" \
        : "=r"(r0), "=r"(r1), "=r"(r2), "=r"(r3) : "r"(addr))

#define LDM_X4_T(r0, r1, r2, r3, addr)                                         \
    asm volatile("ldmatrix.sync.aligned.m8n8.x4.trans.shared.b16 {%0,%1,%2,%3}, [%4];" \
        : "=r"(r0), "=r"(r1), "=r"(r2), "=r"(r3) : "r"(addr))

// ---------------------------------------------------------------------------
// Weight transpose + fp16 convert
// ---------------------------------------------------------------------------
__global__ void transpose_h_kernel(const float* __restrict__ in, __half* __restrict__ out,
                                   int R, int Cn) {
    __shared__ float t[32][33];
    int bx = blockIdx.x * 32, by = blockIdx.y * 32;
#pragma unroll
    for (int i = 0; i < 32; i += 8)
        t[threadIdx.y + i][threadIdx.x] = in[(size_t)(by + threadIdx.y + i) * Cn + bx + threadIdx.x];
    __syncthreads();
#pragma unroll
    for (int i = 0; i < 32; i += 8)
        out[(size_t)(bx + threadIdx.y + i) * R + by + threadIdx.x] =
            __float2half(t[threadIdx.x][threadIdx.y + i]);
}

// ---------------------------------------------------------------------------
// f32 -> fp16 bulk convert (8 elems/thread)
// ---------------------------------------------------------------------------
__global__ void hconv_kernel(const float* __restrict__ src, __half* __restrict__ dst) {
    size_t i = (size_t)blockIdx.x * blockDim.x + threadIdx.x;
    const float4* p = reinterpret_cast<const float4*>(src) + 2 * i;
    float4 a = p[0], b = p[1];
    uint4 u;
    u.x = f2h2(a.x, a.y); u.y = f2h2(a.z, a.w);
    u.z = f2h2(b.x, b.y); u.w = f2h2(b.z, b.w);
    reinterpret_cast<uint4*>(dst)[i] = u;
}

// ---------------------------------------------------------------------------
// fp16 mma.sync GEMM v3: CTA 128x128, BK=32, 4 warps (2m x 2n, 128 threads),
// warp tile 64x64 (4 m-frags x 8 n-frags). Crossbar bytes/MMA: 187 (was 250).
// Loaders: 1 thread per row, 4 x uint4 = full 32-half row coverage.
// ---------------------------------------------------------------------------
#define GSTR 20
#define GEMM_BUF_BYTES (128 * GSTR * 4)

__global__ void __launch_bounds__(128)
gemm_h_kernel(const __half* __restrict__ Ah, const __half* __restrict__ BTh,
              const float* __restrict__ bias, float* __restrict__ Cmat,
              int M, int N, int K) {
    __shared__ uint32_t As2[2][128 * GSTR];
    __shared__ uint32_t Bs2[2][128 * GSTR];

    const int tid = threadIdx.x;
    const int wid = tid >> 5;
    const int lane = tid & 31;
    const int gID = lane >> 2;
    const int tig = lane & 3;
    const int grp = lane >> 3;
    const int l8 = lane & 7;
    const int wm = (wid & 1) * 64;
    const int wn = (wid >> 1) * 64;
    const int bm = blockIdx.y * 128;
    const int bn = blockIdx.x * 128;

    // 1 thread per row (128 rows each side), full 32-half row per thread
    const __half* Agp = Ah + (size_t)(bm + tid) * K;
    const __half* Bgp = BTh + (size_t)(bn + tid) * K;

    const uint32_t asBase = smem_u32(As2);
    const uint32_t bsBase = smem_u32(Bs2);
    uint32_t aAddr[4], bAddr[4];
#pragma unroll
    for (int mi = 0; mi < 4; mi++)
        aAddr[mi] = asBase + (((wm + mi * 16 + (grp & 1) * 8 + l8) * GSTR) + (grp >> 1) * 4) * 4;
#pragma unroll
    for (int ni2 = 0; ni2 < 4; ni2++)
        bAddr[ni2] = bsBase + (((wn + ni2 * 16 + (grp >> 1) * 8 + l8) * GSTR) + (grp & 1) * 4) * 4;

    float acc[4][8][4];
#pragma unroll
    for (int mi = 0; mi < 4; mi++)
#pragma unroll
        for (int ni = 0; ni < 8; ni++)
#pragma unroll
            for (int r = 0; r < 4; r++) acc[mi][ni][r] = 0.f;

    uint4 rA[4], rB[4];
#pragma unroll
    for (int i = 0; i < 4; i++) {
        rA[i] = *reinterpret_cast<const uint4*>(Agp + i * 8);
        rB[i] = *reinterpret_cast<const uint4*>(Bgp + i * 8);
    }
#pragma unroll
    for (int i = 0; i < 4; i++) {
        *reinterpret_cast<uint4*>(&As2[0][tid * GSTR + i * 4]) = rA[i];
        *reinterpret_cast<uint4*>(&Bs2[0][tid * GSTR + i * 4]) = rB[i];
    }
    __syncthreads();

    const int S = K / 32;
    for (int s = 0; s < S; s++) {
        const int buf = s & 1;
        const uint32_t bufOff = (uint32_t)buf * GEMM_BUF_BYTES;
        if (s + 1 < S) {
            Agp += 32; Bgp += 32;
#pragma unroll
            for (int i = 0; i < 4; i++) {
                rA[i] = *reinterpret_cast<const uint4*>(Agp + i * 8);
                rB[i] = *reinterpret_cast<const uint4*>(Bgp + i * 8);
            }
        }

#pragma unroll
        for (int j = 0; j < 2; j++) {
            const uint32_t jOff = bufOff + j * 32;
            uint32_t af[4][4], bf[8][2];
#pragma unroll
            for (int mi = 0; mi < 4; mi++)
                LDM_X4(af[mi][0], af[mi][1], af[mi][2], af[mi][3], aAddr[mi] + jOff);
#pragma unroll
            for (int ni2 = 0; ni2 < 4; ni2++)
                LDM_X4(bf[2 * ni2][0], bf[2 * ni2][1], bf[2 * ni2 + 1][0], bf[2 * ni2 + 1][1],
                       bAddr[ni2] + jOff);
#pragma unroll
            for (int mi = 0; mi < 4; mi++)
#pragma unroll
                for (int ni = 0; ni < 8; ni++)
                    MMA_F16(acc[mi][ni], af[mi][0], af[mi][1], af[mi][2], af[mi][3],
                            bf[ni][0], bf[ni][1]);
        }

        if (s + 1 < S) {
#pragma unroll
            for (int i = 0; i < 4; i++) {
                *reinterpret_cast<uint4*>(&As2[buf ^ 1][tid * GSTR + i * 4]) = rA[i];
                *reinterpret_cast<uint4*>(&Bs2[buf ^ 1][tid * GSTR + i * 4]) = rB[i];
            }
            __syncthreads();
        }
    }

#pragma unroll
    for (int mi = 0; mi < 4; mi++) {
        int row0 = bm + wm + mi * 16 + gID;
#pragma unroll
        for (int ni = 0; ni < 8; ni++) {
            int col = bn + wn + ni * 8 + 2 * tig;
            float b0 = bias[col], b1 = bias[col + 1];
            float2 v0 = make_float2(acc[mi][ni][0] + b0, acc[mi][ni][1] + b1);
            float2 v1 = make_float2(acc[mi][ni][2] + b0, acc[mi][ni][3] + b1);
            *reinterpret_cast<float2*>(Cmat + (size_t)row0 * N + col) = v0;
            *reinterpret_cast<float2*>(Cmat + (size_t)(row0 + 8) * N + col) = v1;
        }
    }
}

// ----------------------------------------------------------------------------
// Head LayerNorm on q,k + v passthrough -> fp16 [bh][n][d] (R11 exact).
// ----------------------------------------------------------------------------
__global__ void qknormv_kernel(const float* __restrict__ gamma_q,
                               const float* __restrict__ gamma_k) {
    int gw = (blockIdx.x * blockDim.x + threadIdx.x) >> 5;
    int lane = threadIdx.x & 31;
    int comp = gw % 3;
    int r = gw / 3;
    int h = r & (HH - 1);
    int bn = r >> 4;
    int b = bn >> 11, n = bn & (NN - 1);

    const float* ptr = g_qkv + (size_t)bn * C3 + comp * CC + h * DD;
    float2 v = *reinterpret_cast<const float2*>(ptr + lane * 2);

    size_t dst = ((size_t)(b * HH + h) * NN + n) * DD + lane * 2;

    if (comp == 2) {
        *reinterpret_cast<uint32_t*>(g_vh + dst) = f2h2(v.x, v.y);
        return;
    }

    float s = v.x + v.y;
#pragma unroll
    for (int off = 16; off >= 1; off >>= 1) s += __shfl_xor_sync(0xffffffffu, s, off);
    float mu = s * (1.0f / 64.0f);

    float dx = v.x - mu, dy = v.y - mu;
    float e = dx * dx + dy * dy;
#pragma unroll
    for (int off = 16; off >= 1; off >>= 1) e += __shfl_xor_sync(0xffffffffu, e, off);
    float rs = rsqrtf(e * (1.0f / 64.0f) + EPSV);

    const float* gamma = comp ? gamma_k : gamma_q;
    float sc = comp ? 1.0f : 0.125f;
    float ox = dx * rs * gamma[lane * 2 + 0] * sc;
    float oy = dy * rs * gamma[lane * 2 + 1] * sc;
    __half* out = comp ? g_kh : g_qh;
    *reinterpret_cast<uint32_t*>(out + dst) = f2h2(ox, oy);
}

// ----------------------------------------------------------------------------
// Flash attention v5 (R15 exact): K/V double buffer + register prefetch,
// one sync per iteration, Q frags hoisted, P register-resident.
// ----------------------------------------------------------------------------
#define FSTR 36
#define KVBUF (64 * FSTR)
#define FLASH_SMEM ((128 * FSTR + 4 * KVBUF) * 4)

__global__ void __launch_bounds__(128) flash_h_kernel() {
    extern __shared__ uint32_t sm[];
    uint32_t* Qs = sm;
    uint32_t* Ks0 = Qs + 128 * FSTR;
    uint32_t* Vs0 = Ks0 + 2 * KVBUF;

    const int tid = threadIdx.x;
    const int wid = tid >> 5;
    const int lane = tid & 31;
    const int gID = lane >> 2;
    const int tig = lane & 3;
    const int grp = lane >> 3;
    const int l8 = lane & 7;
    const int qt = blockIdx.x;
    const int bh = blockIdx.y;
    const int b = bh >> 4;
    const int h = bh & 15;
    const int wq0 = wid * 32;

    uint32_t qAddr[2];
#pragma unroll
    for (int mi = 0; mi < 2; mi++)
        qAddr[mi] = smem_u32(Qs) +
            (((wq0 + mi * 16 + (grp & 1) * 8 + l8) * FSTR) + (grp >> 1) * 4) * 4;
    uint32_t kAddr[4];
#pragma unroll
    for (int n2 = 0; n2 < 4; n2++)
        kAddr[n2] = smem_u32(Ks0) +
            (((n2 * 16 + (grp >> 1) * 8 + l8) * FSTR) + (grp & 1) * 4) * 4;
    const uint32_t vAddr0 = smem_u32(Vs0) +
        ((((grp & 1) * 8 + l8) * FSTR) + (grp >> 1) * 4) * 4;

    const uint32_t* qg = reinterpret_cast<const uint32_t*>(g_qh) +
                         ((size_t)bh * NN + qt * 128) * 32;
#pragma unroll
    for (int i = 0; i < 8; i++) {
        int idx = tid + i * 128;
        int row = idx >> 3, c4 = (idx & 7) * 4;
        uint4 u = *reinterpret_cast<const uint4*>(qg + row * 32 + c4);
        *reinterpret_cast<uint4*>(&Qs[row * FSTR + c4]) = u;
    }
    __syncthreads();

    uint32_t qf[2][4][4];
#pragma unroll
    for (int mi = 0; mi < 2; mi++)
#pragma unroll
        for (int j = 0; j < 4; j++)
            LDM_X4(qf[mi][j][0], qf[mi][j][1], qf[mi][j][2], qf[mi][j][3],
                   qAddr[mi] + j * 32);

    float m[2][2], l[2][2], o[2][8][4];
#pragma unroll
    for (int mi = 0; mi < 2; mi++) {
        m[mi][0] = -1e30f; m[mi][1] = -1e30f;
        l[mi][0] = 0.f; l[mi][1] = 0.f;
#pragma unroll
        for (int nf = 0; nf < 8; nf++)
#pragma unroll
            for (int j = 0; j < 4; j++) o[mi][nf][j] = 0.f;
    }

    const uint32_t* kgBase = reinterpret_cast<const uint32_t*>(g_kh) + (size_t)bh * NN * 32;
    const uint32_t* vgBase = reinterpret_cast<const uint32_t*>(g_vh) + (size_t)bh * NN * 32;

    uint4 rK[4], rV[4];
#pragma unroll
    for (int i = 0; i < 4; i++) {
        int idx = tid + i * 128;
        int row = idx >> 3, c4 = (idx & 7) * 4;
        rK[i] = *reinterpret_cast<const uint4*>(kgBase + row * 32 + c4);
        rV[i] = *reinterpret_cast<const uint4*>(vgBase + row * 32 + c4);
    }

    for (int kt = 0; kt < NN / 64; kt++) {
        const int buf = kt & 1;
        const uint32_t bufOff = (uint32_t)buf * (KVBUF * 4);
        uint32_t* Kw = Ks0 + buf * KVBUF;
        uint32_t* Vw = Vs0 + buf * KVBUF;

#pragma unroll
        for (int i = 0; i < 4; i++) {
            int idx = tid + i * 128;
            int row = idx >> 3, c4 = (idx & 7) * 4;
            *reinterpret_cast<uint4*>(&Kw[row * FSTR + c4]) = rK[i];
            *reinterpret_cast<uint4*>(&Vw[row * FSTR + c4]) = rV[i];
        }
        __syncthreads();

        if (kt + 1 < NN / 64) {
            const uint32_t* kg = kgBase + (size_t)(kt + 1) * 64 * 32;
            const uint32_t* vg = vgBase + (size_t)(kt + 1) * 64 * 32;
#pragma unroll
            for (int i = 0; i < 4; i++) {
                int idx = tid + i * 128;
                int row = idx >> 3, c4 = (idx & 7) * 4;
                rK[i] = *reinterpret_cast<const uint4*>(kg + row * 32 + c4);
                rV[i] = *reinterpret_cast<const uint4*>(vg + row * 32 + c4);
            }
        }

        float s[2][8][4];
#pragma unroll
        for (int mi = 0; mi < 2; mi++)
#pragma unroll
            for (int nf = 0; nf < 8; nf++)
#pragma unroll
                for (int j = 0; j < 4; j++) s[mi][nf][j] = 0.f;

#pragma unroll
        for (int j = 0; j < 4; j++) {
            uint32_t bf[8][2];
#pragma unroll
            for (int n2 = 0; n2 < 4; n2++)
                LDM_X4(bf[2 * n2][0], bf[2 * n2][1], bf[2 * n2 + 1][0], bf[2 * n2 + 1][1],
                       kAddr[n2] + bufOff + j * 32);
#pragma unroll
            for (int nf = 0; nf < 8; nf++) {
                MMA_F16(s[0][nf], qf[0][j][0], qf[0][j][1], qf[0][j][2], qf[0][j][3],
                        bf[nf][0], bf[nf][1]);
                MMA_F16(s[1][nf], qf[1][j][0], qf[1][j][1], qf[1][j][2], qf[1][j][3],
                        bf[nf][0], bf[nf][1]);
            }
        }

        uint32_t ph[2][4][4];
#pragma unroll
        for (int mi = 0; mi < 2; mi++) {
            float mx0 = -1e30f, mx1 = -1e30f;
#pragma unroll
            for (int nf = 0; nf < 8; nf++) {
                mx0 = fmaxf(mx0, fmaxf(s[mi][nf][0], s[mi][nf][1]));
                mx1 = fmaxf(mx1, fmaxf(s[mi][nf][2], s[mi][nf][3]));
            }
            mx0 = fmaxf(mx0, __shfl_xor_sync(0xffffffffu, mx0, 1));
            mx0 = fmaxf(mx0, __shfl_xor_sync(0xffffffffu, mx0, 2));
            mx1 = fmaxf(mx1, __shfl_xor_sync(0xffffffffu, mx1, 1));
            mx1 = fmaxf(mx1, __shfl_xor_sync(0xffffffffu, mx1, 2));

            float mn0 = fmaxf(m[mi][0], mx0), mn1 = fmaxf(m[mi][1], mx1);
            float corr0 = __expf(m[mi][0] - mn0), corr1 = __expf(m[mi][1] - mn1);
            float rs0 = 0.f, rs1 = 0.f;
#pragma unroll
            for (int nf = 0; nf < 8; nf++) {
                s[mi][nf][0] = __expf(s[mi][nf][0] - mn0);
                s[mi][nf][1] = __expf(s[mi][nf][1] - mn0);
                s[mi][nf][2] = __expf(s[mi][nf][2] - mn1);
                s[mi][nf][3] = __expf(s[mi][nf][3] - mn1);
                rs0 += s[mi][nf][0] + s[mi][nf][1];
                rs1 += s[mi][nf][2] + s[mi][nf][3];
            }
#pragma unroll
            for (int j = 0; j < 4; j++) {
                ph[mi][j][0] = f2h2(s[mi][2 * j][0], s[mi][2 * j][1]);
                ph[mi][j][1] = f2h2(s[mi][2 * j][2], s[mi][2 * j][3]);
                ph[mi][j][2] = f2h2(s[mi][2 * j + 1][0], s[mi][2 * j + 1][1]);
                ph[mi][j][3] = f2h2(s[mi][2 * j + 1][2], s[mi][2 * j + 1][3]);
            }
            rs0 += __shfl_xor_sync(0xffffffffu, rs0, 1);
            rs0 += __shfl_xor_sync(0xffffffffu, rs0, 2);
            rs1 += __shfl_xor_sync(0xffffffffu, rs1, 1);
            rs1 += __shfl_xor_sync(0xffffffffu, rs1, 2);
            l[mi][0] = l[mi][0] * corr0 + rs0;
            l[mi][1] = l[mi][1] * corr1 + rs1;
            m[mi][0] = mn0; m[mi][1] = mn1;
#pragma unroll
            for (int nf = 0; nf < 8; nf++) {
                o[mi][nf][0] *= corr0; o[mi][nf][1] *= corr0;
                o[mi][nf][2] *= corr1; o[mi][nf][3] *= corr1;
            }
        }

#pragma unroll
        for (int j = 0; j < 4; j++) {
            const uint32_t vj = vAddr0 + bufOff + j * 16 * FSTR * 4;
            uint32_t bt[8][2];
#pragma unroll
            for (int nf0 = 0; nf0 < 8; nf0 += 2)
                LDM_X4_T(bt[nf0][0], bt[nf0][1], bt[nf0 + 1][0], bt[nf0 + 1][1],
                         vj + nf0 * 16);
#pragma unroll
            for (int nf = 0; nf < 8; nf++) {
                MMA_F16(o[0][nf], ph[0][j][0], ph[0][j][1], ph[0][j][2], ph[0][j][3],
                        bt[nf][0], bt[nf][1]);
                MMA_F16(o[1][nf], ph[1][j][0], ph[1][j][1], ph[1][j][2], ph[1][j][3],
                        bt[nf][0], bt[nf][1]);
            }
        }
    }

#pragma unroll
    for (int mi = 0; mi < 2; mi++) {
        float inv0 = 1.0f / l[mi][0], inv1 = 1.0f / l[mi][1];
        int row0 = qt * 128 + wq0 + mi * 16 + gID;
#pragma unroll
        for (int nf = 0; nf < 8; nf++) {
            int col = h * DD + nf * 8 + 2 * tig;
            *reinterpret_cast<uint32_t*>(g_oh + (size_t)(b * NN + row0) * CC + col) =
                f2h2(o[mi][nf][0] * inv0, o[mi][nf][1] * inv0);
            *reinterpret_cast<uint32_t*>(g_oh + (size_t)(b * NN + row0 + 8) * CC + col) =
                f2h2(o[mi][nf][2] * inv1, o[mi][nf][3] * inv1);
        }
    }
}

// ----------------------------------------------------------------------------
extern "C" void kernel_launch(void* const* d_in, const int* in_sizes, int n_in,
                              void* d_out, int out_size) {
    const float* x      = (const float*)d_in[0];
    const float* w_qkv  = (const float*)d_in[1];
    const float* b_qkv  = (const float*)d_in[2];
    const float* gq     = (const float*)d_in[3];
    const float* gk     = (const float*)d_in[4];
    const float* w_proj = (const float*)d_in[5];
    const float* b_proj = (const float*)d_in[6];
    float* out = (float*)d_out;

    float* qkv_ptr = nullptr;
    __half *xh = nullptr, *oh = nullptr, *wqkvTh = nullptr, *wprojTh = nullptr;
    cudaGetSymbolAddress((void**)&qkv_ptr, g_qkv);
    cudaGetSymbolAddress((void**)&xh, g_xh);
    cudaGetSymbolAddress((void**)&oh, g_oh);
    cudaGetSymbolAddress((void**)&wqkvTh, g_wqkvTh);
    cudaGetSymbolAddress((void**)&wprojTh, g_wprojTh);

    // 0) weight transpose+convert, x convert
    {
        dim3 blk(32, 8);
        transpose_h_kernel<<<dim3(C3 / 32, CC / 32), blk>>>(w_qkv, wqkvTh, CC, C3);
        transpose_h_kernel<<<dim3(CC / 32, CC / 32), blk>>>(w_proj, wprojTh, CC, CC);
        hconv_kernel<<<(MM * CC / 8) / 256, 256>>>(x, xh);
    }

    // 1) QKV GEMM (4 warps, warp tile 64x64)
    {
        dim3 grid(C3 / 128, MM / 128);
        gemm_h_kernel<<<grid, 128>>>(xh, wqkvTh, b_qkv, qkv_ptr, MM, C3, CC);
    }

    // 2) head layernorm q,k + v passthrough -> fp16 [bh][n][d]
    {
        int total_warps = 3 * MM * HH;
        qknormv_kernel<<<total_warps / 8, 256>>>(gq, gk);
    }

    // 3) flash attention v5
    {
        cudaFuncSetAttribute(flash_h_kernel, cudaFuncAttributeMaxDynamicSharedMemorySize, FLASH_SMEM);
        dim3 grid(NN / 128, BB * HH);
        flash_h_kernel<<<grid, 128, FLASH_SMEM>>>();
    }

    // 4) output projection
    {
        dim3 grid(CC / 128, MM / 128);
        gemm_h_kernel<<<grid, 128>>>(oh, wprojTh, b_proj, out, MM, CC, CC);
    }
}

// round 17
// speedup vs baseline: 1.1583x; 1.1583x over previous
#include <cuda_runtime.h>
#include <cuda_fp16.h>
#include <cstdint>
#include <math.h>

// Problem constants
#define BB 4
#define NN 2048
#define CC 1024
#define HH 16
#define DD 64
#define MM (BB * NN)          // 8192
#define C3 (3 * CC)           // 3072
#define EPSV 1e-6f

// Scratch (16B-aligned)
__device__ __align__(16) float  g_qkv[(size_t)MM * C3];       // 96 MB
__device__ __align__(16) __half g_xh[(size_t)MM * CC];        // 16 MB
__device__ __align__(16) __half g_oh[(size_t)MM * CC];        // 16 MB
__device__ __align__(16) __half g_wqkvTh[(size_t)C3 * CC];    // 6 MB
__device__ __align__(16) __half g_wprojTh[(size_t)CC * CC];   // 2 MB
__device__ __align__(16) __half g_qh[(size_t)BB * HH * NN * DD]; // 16 MB
__device__ __align__(16) __half g_kh[(size_t)BB * HH * NN * DD]; // 16 MB
__device__ __align__(16) __half g_vh[(size_t)BB * HH * NN * DD]; // 16 MB

__device__ __forceinline__ uint32_t f2h2(float lo, float hi) {
    __half2 h = __float22half2_rn(make_float2(lo, hi));
    return *reinterpret_cast<uint32_t*>(&h);
}
__device__ __forceinline__ uint32_t smem_u32(const void* p) {
    uint32_t a;
    asm("{ .reg .u64 t; cvta.to.shared.u64 t, %1; cvt.u32.u64 %0, t; }" : "=r"(a) : "l"(p));
    return a;
}

#define MMA_F16(c, a0, a1, a2, a3, b0, b1)                                     \
    asm volatile(                                                               \
        "mma.sync.aligned.m16n8k16.row.col.f32.f16.f16.f32 "                    \
        "{%0,%1,%2,%3}, {%4,%5,%6,%7}, {%8,%9}, {%0,%1,%2,%3};"                 \
        : "+f"((c)[0]), "+f"((c)[1]), "+f"((c)[2]), "+f"((c)[3])                \
        : "r"(a0), "r"(a1), "r"(a2), "r"(a3), "r"(b0), "r"(b1))

#define LDM_X4(r0, r1, r2, r3, addr)                                           \
    asm volatile("ldmatrix.sync.aligned.m8n8.x4.shared.b16 {%0,%1,%2,%3}, [%4];" \
        : "=r"(r0), "=r"(r1), "=r"(r2), "=r"(r3) : "r"(addr))

#define LDM_X4_T(r0, r1, r2, r3, addr)                                         \
    asm volatile("ldmatrix.sync.aligned.m8n8.x4.trans.shared.b16 {%0,%1,%2,%3}, [%4];" \
        : "=r"(r0), "=r"(r1), "=r"(r2), "=r"(r3) : "r"(addr))

// ---------------------------------------------------------------------------
// Weight transpose + fp16 convert
// ---------------------------------------------------------------------------
__global__ void transpose_h_kernel(const float* __restrict__ in, __half* __restrict__ out,
                                   int R, int Cn) {
    __shared__ float t[32][33];
    int bx = blockIdx.x * 32, by = blockIdx.y * 32;
#pragma unroll
    for (int i = 0; i < 32; i += 8)
        t[threadIdx.y + i][threadIdx.x] = in[(size_t)(by + threadIdx.y + i) * Cn + bx + threadIdx.x];
    __syncthreads();
#pragma unroll
    for (int i = 0; i < 32; i += 8)
        out[(size_t)(bx + threadIdx.y + i) * R + by + threadIdx.x] =
            __float2half(t[threadIdx.x][threadIdx.y + i]);
}

// ---------------------------------------------------------------------------
// f32 -> fp16 bulk convert (8 elems/thread)
// ---------------------------------------------------------------------------
__global__ void hconv_kernel(const float* __restrict__ src, __half* __restrict__ dst) {
    size_t i = (size_t)blockIdx.x * blockDim.x + threadIdx.x;
    const float4* p = reinterpret_cast<const float4*>(src) + 2 * i;
    float4 a = p[0], b = p[1];
    uint4 u;
    u.x = f2h2(a.x, a.y); u.y = f2h2(a.z, a.w);
    u.z = f2h2(b.x, b.y); u.w = f2h2(b.z, b.w);
    reinterpret_cast<uint4*>(dst)[i] = u;
}

// ---------------------------------------------------------------------------
// fp16 mma.sync GEMM with ldmatrix (R10-exact — proven 232us config).
// CTA 128x128, BK=32, 8 warps (2m x 4n), warp tile 64x32, double-buffered.
// ---------------------------------------------------------------------------
#define GSTR 20
#define GEMM_BUF_BYTES (128 * GSTR * 4)

__global__ void __launch_bounds__(256)
gemm_h_kernel(const __half* __restrict__ Ah, const __half* __restrict__ BTh,
              const float* __restrict__ bias, float* __restrict__ Cmat,
              int M, int N, int K) {
    __shared__ uint32_t As2[2][128 * GSTR];
    __shared__ uint32_t Bs2[2][128 * GSTR];

    const int tid = threadIdx.x;
    const int wid = tid >> 5;
    const int lane = tid & 31;
    const int gID = lane >> 2;
    const int tig = lane & 3;
    const int grp = lane >> 3;
    const int l8 = lane & 7;
    const int wm = (wid & 1) * 64;
    const int wn = (wid >> 1) * 32;
    const int bm = blockIdx.y * 128;
    const int bn = blockIdx.x * 128;

    const int lrow = tid >> 1;
    const int lhalf = (tid & 1) * 8;
    const __half* Agp = Ah + (size_t)(bm + lrow) * K + (tid & 1) * 16;
    const __half* Bgp = BTh + (size_t)(bn + lrow) * K + (tid & 1) * 16;

    const uint32_t asBase = smem_u32(As2);
    const uint32_t bsBase = smem_u32(Bs2);
    uint32_t aAddr[4], bAddr[2];
#pragma unroll
    for (int mi = 0; mi < 4; mi++)
        aAddr[mi] = asBase + (((wm + mi * 16 + (grp & 1) * 8 + l8) * GSTR) + (grp >> 1) * 4) * 4;
#pragma unroll
    for (int ni2 = 0; ni2 < 2; ni2++)
        bAddr[ni2] = bsBase + (((wn + ni2 * 16 + (grp >> 1) * 8 + l8) * GSTR) + (grp & 1) * 4) * 4;

    float acc[4][4][4];
#pragma unroll
    for (int mi = 0; mi < 4; mi++)
#pragma unroll
        for (int ni = 0; ni < 4; ni++)
#pragma unroll
            for (int r = 0; r < 4; r++) acc[mi][ni][r] = 0.f;

    uint4 rA0 = *reinterpret_cast<const uint4*>(Agp);
    uint4 rA1 = *reinterpret_cast<const uint4*>(Agp + 8);
    uint4 rB0 = *reinterpret_cast<const uint4*>(Bgp);
    uint4 rB1 = *reinterpret_cast<const uint4*>(Bgp + 8);
    *reinterpret_cast<uint4*>(&As2[0][lrow * GSTR + lhalf]) = rA0;
    *reinterpret_cast<uint4*>(&As2[0][lrow * GSTR + lhalf + 4]) = rA1;
    *reinterpret_cast<uint4*>(&Bs2[0][lrow * GSTR + lhalf]) = rB0;
    *reinterpret_cast<uint4*>(&Bs2[0][lrow * GSTR + lhalf + 4]) = rB1;
    __syncthreads();

    const int S = K / 32;
    for (int s = 0; s < S; s++) {
        const int buf = s & 1;
        const uint32_t bufOff = (uint32_t)buf * GEMM_BUF_BYTES;
        if (s + 1 < S) {
            Agp += 32; Bgp += 32;
            rA0 = *reinterpret_cast<const uint4*>(Agp);
            rA1 = *reinterpret_cast<const uint4*>(Agp + 8);
            rB0 = *reinterpret_cast<const uint4*>(Bgp);
            rB1 = *reinterpret_cast<const uint4*>(Bgp + 8);
        }

#pragma unroll
        for (int j = 0; j < 2; j++) {
            const uint32_t jOff = bufOff + j * 32;
            uint32_t af[4][4], bf[4][2];
#pragma unroll
            for (int mi = 0; mi < 4; mi++)
                LDM_X4(af[mi][0], af[mi][1], af[mi][2], af[mi][3], aAddr[mi] + jOff);
            LDM_X4(bf[0][0], bf[0][1], bf[1][0], bf[1][1], bAddr[0] + jOff);
            LDM_X4(bf[2][0], bf[2][1], bf[3][0], bf[3][1], bAddr[1] + jOff);
#pragma unroll
            for (int mi = 0; mi < 4; mi++)
#pragma unroll
                for (int ni = 0; ni < 4; ni++)
                    MMA_F16(acc[mi][ni], af[mi][0], af[mi][1], af[mi][2], af[mi][3],
                            bf[ni][0], bf[ni][1]);
        }

        if (s + 1 < S) {
            *reinterpret_cast<uint4*>(&As2[buf ^ 1][lrow * GSTR + lhalf]) = rA0;
            *reinterpret_cast<uint4*>(&As2[buf ^ 1][lrow * GSTR + lhalf + 4]) = rA1;
            *reinterpret_cast<uint4*>(&Bs2[buf ^ 1][lrow * GSTR + lhalf]) = rB0;
            *reinterpret_cast<uint4*>(&Bs2[buf ^ 1][lrow * GSTR + lhalf + 4]) = rB1;
            __syncthreads();
        }
    }

#pragma unroll
    for (int mi = 0; mi < 4; mi++) {
        int row0 = bm + wm + mi * 16 + gID;
#pragma unroll
        for (int ni = 0; ni < 4; ni++) {
            int col = bn + wn + ni * 8 + 2 * tig;
            float b0 = bias[col], b1 = bias[col + 1];
            float2 v0 = make_float2(acc[mi][ni][0] + b0, acc[mi][ni][1] + b1);
            float2 v1 = make_float2(acc[mi][ni][2] + b0, acc[mi][ni][3] + b1);
            *reinterpret_cast<float2*>(Cmat + (size_t)row0 * N + col) = v0;
            *reinterpret_cast<float2*>(Cmat + (size_t)(row0 + 8) * N + col) = v1;
        }
    }
}

// ----------------------------------------------------------------------------
// Head LayerNorm v2: 4 items per warp, loads batched first (MLP=4).
// item = (row, comp): comp 0=q (LN, x0.125), 1=k (LN), 2=v (passthrough).
// Outputs fp16 [bh][n][d]. Same per-row math/rounding as R11 LN.
// ----------------------------------------------------------------------------
__global__ void qknormv_kernel(const float* __restrict__ gamma_q,
                               const float* __restrict__ gamma_k) {
    int w4 = (blockIdx.x * blockDim.x + threadIdx.x) >> 5;   // warp id
    int lane = threadIdx.x & 31;

    float2 v[4];
    size_t dst[4];
    int comp[4];
#pragma unroll
    for (int jj = 0; jj < 4; jj++) {
        int item = w4 * 4 + jj;            // [0, 3*MM*HH)
        int c = item % 3;
        int r = item / 3;                  // [0, MM*HH)
        int h = r & (HH - 1);
        int bn = r >> 4;                   // b*NN + n
        int b = bn >> 11, n = bn & (NN - 1);
        comp[jj] = c;
        dst[jj] = ((size_t)(b * HH + h) * NN + n) * DD + lane * 2;
        const float* ptr = g_qkv + (size_t)bn * C3 + c * CC + h * DD;
        v[jj] = *reinterpret_cast<const float2*>(ptr + lane * 2);
    }

#pragma unroll
    for (int jj = 0; jj < 4; jj++) {
        if (comp[jj] == 2) {
            *reinterpret_cast<uint32_t*>(g_vh + dst[jj]) = f2h2(v[jj].x, v[jj].y);
            continue;
        }
        float s = v[jj].x + v[jj].y;
#pragma unroll
        for (int off = 16; off >= 1; off >>= 1) s += __shfl_xor_sync(0xffffffffu, s, off);
        float mu = s * (1.0f / 64.0f);

        float dx = v[jj].x - mu, dy = v[jj].y - mu;
        float e = dx * dx + dy * dy;
#pragma unroll
        for (int off = 16; off >= 1; off >>= 1) e += __shfl_xor_sync(0xffffffffu, e, off);
        float rs = rsqrtf(e * (1.0f / 64.0f) + EPSV);

        const float* gamma = comp[jj] ? gamma_k : gamma_q;
        float sc = comp[jj] ? 1.0f : 0.125f;
        float ox = dx * rs * gamma[lane * 2 + 0] * sc;
        float oy = dy * rs * gamma[lane * 2 + 1] * sc;
        __half* out = comp[jj] ? g_kh : g_qh;
        *reinterpret_cast<uint32_t*>(out + dst[jj]) = f2h2(ox, oy);
    }
}

// ----------------------------------------------------------------------------
// Flash attention v5 (R15 exact): K/V double buffer + register prefetch,
// one sync per iteration, Q frags hoisted, P register-resident.
// ----------------------------------------------------------------------------
#define FSTR 36
#define KVBUF (64 * FSTR)
#define FLASH_SMEM ((128 * FSTR + 4 * KVBUF) * 4)

__global__ void __launch_bounds__(128) flash_h_kernel() {
    extern __shared__ uint32_t sm[];
    uint32_t* Qs = sm;
    uint32_t* Ks0 = Qs + 128 * FSTR;
    uint32_t* Vs0 = Ks0 + 2 * KVBUF;

    const int tid = threadIdx.x;
    const int wid = tid >> 5;
    const int lane = tid & 31;
    const int gID = lane >> 2;
    const int tig = lane & 3;
    const int grp = lane >> 3;
    const int l8 = lane & 7;
    const int qt = blockIdx.x;
    const int bh = blockIdx.y;
    const int b = bh >> 4;
    const int h = bh & 15;
    const int wq0 = wid * 32;

    uint32_t qAddr[2];
#pragma unroll
    for (int mi = 0; mi < 2; mi++)
        qAddr[mi] = smem_u32(Qs) +
            (((wq0 + mi * 16 + (grp & 1) * 8 + l8) * FSTR) + (grp >> 1) * 4) * 4;
    uint32_t kAddr[4];
#pragma unroll
    for (int n2 = 0; n2 < 4; n2++)
        kAddr[n2] = smem_u32(Ks0) +
            (((n2 * 16 + (grp >> 1) * 8 + l8) * FSTR) + (grp & 1) * 4) * 4;
    const uint32_t vAddr0 = smem_u32(Vs0) +
        ((((grp & 1) * 8 + l8) * FSTR) + (grp >> 1) * 4) * 4;

    const uint32_t* qg = reinterpret_cast<const uint32_t*>(g_qh) +
                         ((size_t)bh * NN + qt * 128) * 32;
#pragma unroll
    for (int i = 0; i < 8; i++) {
        int idx = tid + i * 128;
        int row = idx >> 3, c4 = (idx & 7) * 4;
        uint4 u = *reinterpret_cast<const uint4*>(qg + row * 32 + c4);
        *reinterpret_cast<uint4*>(&Qs[row * FSTR + c4]) = u;
    }
    __syncthreads();

    uint32_t qf[2][4][4];
#pragma unroll
    for (int mi = 0; mi < 2; mi++)
#pragma unroll
        for (int j = 0; j < 4; j++)
            LDM_X4(qf[mi][j][0], qf[mi][j][1], qf[mi][j][2], qf[mi][j][3],
                   qAddr[mi] + j * 32);

    float m[2][2], l[2][2], o[2][8][4];
#pragma unroll
    for (int mi = 0; mi < 2; mi++) {
        m[mi][0] = -1e30f; m[mi][1] = -1e30f;
        l[mi][0] = 0.f; l[mi][1] = 0.f;
#pragma unroll
        for (int nf = 0; nf < 8; nf++)
#pragma unroll
            for (int j = 0; j < 4; j++) o[mi][nf][j] = 0.f;
    }

    const uint32_t* kgBase = reinterpret_cast<const uint32_t*>(g_kh) + (size_t)bh * NN * 32;
    const uint32_t* vgBase = reinterpret_cast<const uint32_t*>(g_vh) + (size_t)bh * NN * 32;

    uint4 rK[4], rV[4];
#pragma unroll
    for (int i = 0; i < 4; i++) {
        int idx = tid + i * 128;
        int row = idx >> 3, c4 = (idx & 7) * 4;
        rK[i] = *reinterpret_cast<const uint4*>(kgBase + row * 32 + c4);
        rV[i] = *reinterpret_cast<const uint4*>(vgBase + row * 32 + c4);
    }

    for (int kt = 0; kt < NN / 64; kt++) {
        const int buf = kt & 1;
        const uint32_t bufOff = (uint32_t)buf * (KVBUF * 4);
        uint32_t* Kw = Ks0 + buf * KVBUF;
        uint32_t* Vw = Vs0 + buf * KVBUF;

#pragma unroll
        for (int i = 0; i < 4; i++) {
            int idx = tid + i * 128;
            int row = idx >> 3, c4 = (idx & 7) * 4;
            *reinterpret_cast<uint4*>(&Kw[row * FSTR + c4]) = rK[i];
            *reinterpret_cast<uint4*>(&Vw[row * FSTR + c4]) = rV[i];
        }
        __syncthreads();

        if (kt + 1 < NN / 64) {
            const uint32_t* kg = kgBase + (size_t)(kt + 1) * 64 * 32;
            const uint32_t* vg = vgBase + (size_t)(kt + 1) * 64 * 32;
#pragma unroll
            for (int i = 0; i < 4; i++) {
                int idx = tid + i * 128;
                int row = idx >> 3, c4 = (idx & 7) * 4;
                rK[i] = *reinterpret_cast<const uint4*>(kg + row * 32 + c4);
                rV[i] = *reinterpret_cast<const uint4*>(vg + row * 32 + c4);
            }
        }

        float s[2][8][4];
#pragma unroll
        for (int mi = 0; mi < 2; mi++)
#pragma unroll
            for (int nf = 0; nf < 8; nf++)
#pragma unroll
                for (int j = 0; j < 4; j++) s[mi][nf][j] = 0.f;

#pragma unroll
        for (int j = 0; j < 4; j++) {
            uint32_t bf[8][2];
#pragma unroll
            for (int n2 = 0; n2 < 4; n2++)
                LDM_X4(bf[2 * n2][0], bf[2 * n2][1], bf[2 * n2 + 1][0], bf[2 * n2 + 1][1],
                       kAddr[n2] + bufOff + j * 32);
#pragma unroll
            for (int nf = 0; nf < 8; nf++) {
                MMA_F16(s[0][nf], qf[0][j][0], qf[0][j][1], qf[0][j][2], qf[0][j][3],
                        bf[nf][0], bf[nf][1]);
                MMA_F16(s[1][nf], qf[1][j][0], qf[1][j][1], qf[1][j][2], qf[1][j][3],
                        bf[nf][0], bf[nf][1]);
            }
        }

        uint32_t ph[2][4][4];
#pragma unroll
        for (int mi = 0; mi < 2; mi++) {
            float mx0 = -1e30f, mx1 = -1e30f;
#pragma unroll
            for (int nf = 0; nf < 8; nf++) {
                mx0 = fmaxf(mx0, fmaxf(s[mi][nf][0], s[mi][nf][1]));
                mx1 = fmaxf(mx1, fmaxf(s[mi][nf][2], s[mi][nf][3]));
            }
            mx0 = fmaxf(mx0, __shfl_xor_sync(0xffffffffu, mx0, 1));
            mx0 = fmaxf(mx0, __shfl_xor_sync(0xffffffffu, mx0, 2));
            mx1 = fmaxf(mx1, __shfl_xor_sync(0xffffffffu, mx1, 1));
            mx1 = fmaxf(mx1, __shfl_xor_sync(0xffffffffu, mx1, 2));

            float mn0 = fmaxf(m[mi][0], mx0), mn1 = fmaxf(m[mi][1], mx1);
            float corr0 = __expf(m[mi][0] - mn0), corr1 = __expf(m[mi][1] - mn1);
            float rs0 = 0.f, rs1 = 0.f;
#pragma unroll
            for (int nf = 0; nf < 8; nf++) {
                s[mi][nf][0] = __expf(s[mi][nf][0] - mn0);
                s[mi][nf][1] = __expf(s[mi][nf][1] - mn0);
                s[mi][nf][2] = __expf(s[mi][nf][2] - mn1);
                s[mi][nf][3] = __expf(s[mi][nf][3] - mn1);
                rs0 += s[mi][nf][0] + s[mi][nf][1];
                rs1 += s[mi][nf][2] + s[mi][nf][3];
            }
#pragma unroll
            for (int j = 0; j < 4; j++) {
                ph[mi][j][0] = f2h2(s[mi][2 * j][0], s[mi][2 * j][1]);
                ph[mi][j][1] = f2h2(s[mi][2 * j][2], s[mi][2 * j][3]);
                ph[mi][j][2] = f2h2(s[mi][2 * j + 1][0], s[mi][2 * j + 1][1]);
                ph[mi][j][3] = f2h2(s[mi][2 * j + 1][2], s[mi][2 * j + 1][3]);
            }
            rs0 += __shfl_xor_sync(0xffffffffu, rs0, 1);
            rs0 += __shfl_xor_sync(0xffffffffu, rs0, 2);
            rs1 += __shfl_xor_sync(0xffffffffu, rs1, 1);
            rs1 += __shfl_xor_sync(0xffffffffu, rs1, 2);
            l[mi][0] = l[mi][0] * corr0 + rs0;
            l[mi][1] = l[mi][1] * corr1 + rs1;
            m[mi][0] = mn0; m[mi][1] = mn1;
#pragma unroll
            for (int nf = 0; nf < 8; nf++) {
                o[mi][nf][0] *= corr0; o[mi][nf][1] *= corr0;
                o[mi][nf][2] *= corr1; o[mi][nf][3] *= corr1;
            }
        }

#pragma unroll
        for (int j = 0; j < 4; j++) {
            const uint32_t vj = vAddr0 + bufOff + j * 16 * FSTR * 4;
            uint32_t bt[8][2];
#pragma unroll
            for (int nf0 = 0; nf0 < 8; nf0 += 2)
                LDM_X4_T(bt[nf0][0], bt[nf0][1], bt[nf0 + 1][0], bt[nf0 + 1][1],
                         vj + nf0 * 16);
#pragma unroll
            for (int nf = 0; nf < 8; nf++) {
                MMA_F16(o[0][nf], ph[0][j][0], ph[0][j][1], ph[0][j][2], ph[0][j][3],
                        bt[nf][0], bt[nf][1]);
                MMA_F16(o[1][nf], ph[1][j][0], ph[1][j][1], ph[1][j][2], ph[1][j][3],
                        bt[nf][0], bt[nf][1]);
            }
        }
    }

#pragma unroll
    for (int mi = 0; mi < 2; mi++) {
        float inv0 = 1.0f / l[mi][0], inv1 = 1.0f / l[mi][1];
        int row0 = qt * 128 + wq0 + mi * 16 + gID;
#pragma unroll
        for (int nf = 0; nf < 8; nf++) {
            int col = h * DD + nf * 8 + 2 * tig;
            *reinterpret_cast<uint32_t*>(g_oh + (size_t)(b * NN + row0) * CC + col) =
                f2h2(o[mi][nf][0] * inv0, o[mi][nf][1] * inv0);
            *reinterpret_cast<uint32_t*>(g_oh + (size_t)(b * NN + row0 + 8) * CC + col) =
                f2h2(o[mi][nf][2] * inv1, o[mi][nf][3] * inv1);
        }
    }
}

// ----------------------------------------------------------------------------
extern "C" void kernel_launch(void* const* d_in, const int* in_sizes, int n_in,
                              void* d_out, int out_size) {
    const float* x      = (const float*)d_in[0];
    const float* w_qkv  = (const float*)d_in[1];
    const float* b_qkv  = (const float*)d_in[2];
    const float* gq     = (const float*)d_in[3];
    const float* gk     = (const float*)d_in[4];
    const float* w_proj = (const float*)d_in[5];
    const float* b_proj = (const float*)d_in[6];
    float* out = (float*)d_out;

    float* qkv_ptr = nullptr;
    __half *xh = nullptr, *oh = nullptr, *wqkvTh = nullptr, *wprojTh = nullptr;
    cudaGetSymbolAddress((void**)&qkv_ptr, g_qkv);
    cudaGetSymbolAddress((void**)&xh, g_xh);
    cudaGetSymbolAddress((void**)&oh, g_oh);
    cudaGetSymbolAddress((void**)&wqkvTh, g_wqkvTh);
    cudaGetSymbolAddress((void**)&wprojTh, g_wprojTh);

    // 0) weight transpose+convert, x convert
    {
        dim3 blk(32, 8);
        transpose_h_kernel<<<dim3(C3 / 32, CC / 32), blk>>>(w_qkv, wqkvTh, CC, C3);
        transpose_h_kernel<<<dim3(CC / 32, CC / 32), blk>>>(w_proj, wprojTh, CC, CC);
        hconv_kernel<<<(MM * CC / 8) / 256, 256>>>(x, xh);
    }

    // 1) QKV GEMM (R10-exact config)
    {
        dim3 grid(C3 / 128, MM / 128);
        gemm_h_kernel<<<grid, 256>>>(xh, wqkvTh, b_qkv, qkv_ptr, MM, C3, CC);
    }

    // 2) head layernorm q,k + v passthrough (4 items/warp, MLP=4)
    {
        int total_items = 3 * MM * HH;               // 393216
        int warps = total_items / 4;                 // 98304
        qknormv_kernel<<<warps / 8, 256>>>(gq, gk);  // 8 warps per block
    }

    // 3) flash attention v5
    {
        cudaFuncSetAttribute(flash_h_kernel, cudaFuncAttributeMaxDynamicSharedMemorySize, FLASH_SMEM);
        dim3 grid(NN / 128, BB * HH);
        flash_h_kernel<<<grid, 128, FLASH_SMEM>>>();
    }

    // 4) output projection
    {
        dim3 grid(CC / 128, MM / 128);
        gemm_h_kernel<<<grid, 256>>>(oh, wprojTh, b_proj, out, MM, CC, CC);
    }
}